// round 1
// baseline (speedup 1.0000x reference)
#include <cuda_runtime.h>

#define T   4
#define HH  64
#define HE  16
#define HD  128
#define KIN 145          // 2*HH + 1 + HE
#define NKIN 192         // HH + HD
#define EPB 4            // edges per block
#define NPB 4            // nodes per block
#define RPB 16           // rows per block (EPB*T == NPB*T)
#define MAXN 20000
#define EPSF 1e-8f

// Scratch (device globals — no allocation allowed)
__device__ float g_mi[MAXN * HD * T];   // segment-summed m_ij  [N,HD,T]
__device__ float g_agg[MAXN * 3 * T];   // coord aggregate      [N,3,T]
__device__ float g_cnt[MAXN];           // edge counts          [N]

__device__ __forceinline__ float silu_f(float v) {
    return v / (1.0f + __expf(-v));
}

#define FMA16(acc, pp, w) do {                                      \
    float4 v0 = (pp)[0], v1 = (pp)[1], v2 = (pp)[2], v3 = (pp)[3];  \
    acc[0]  += v0.x * (w); acc[1]  += v0.y * (w);                   \
    acc[2]  += v0.z * (w); acc[3]  += v0.w * (w);                   \
    acc[4]  += v1.x * (w); acc[5]  += v1.y * (w);                   \
    acc[6]  += v1.z * (w); acc[7]  += v1.w * (w);                   \
    acc[8]  += v2.x * (w); acc[9]  += v2.y * (w);                   \
    acc[10] += v2.z * (w); acc[11] += v2.w * (w);                   \
    acc[12] += v3.x * (w); acc[13] += v3.y * (w);                   \
    acc[14] += v3.z * (w); acc[15] += v3.w * (w);                   \
} while (0)

// One 16-row x OUTD tile GEMM: dst[j][i] = act(bias[j] + sum_k src[k][i]*W[k*OUTD+j])
// Caller guarantees j < OUTD. src rows are 16 floats, 16B-aligned.
template<int K, int OUTD, bool ACT>
__device__ __forceinline__ void gemm_tile(
    const float (* __restrict__ src)[RPB],
    const float* __restrict__ W,
    const float* __restrict__ bias,
    float (* __restrict__ dst)[RPB],
    int j)
{
    float acc[RPB];
    float bj = bias[j];
#pragma unroll
    for (int i = 0; i < RPB; i++) acc[i] = bj;
#pragma unroll 4
    for (int k = 0; k < K; k++) {
        float w = W[k * OUTD + j];
        const float4* pp = reinterpret_cast<const float4*>(src[k]);
        FMA16(acc, pp, w);
    }
#pragma unroll
    for (int i = 0; i < RPB; i++)
        dst[j][i] = ACT ? silu_f(acc[i]) : acc[i];
}

__global__ void zero_kernel(int n) {
    int stride = gridDim.x * blockDim.x;
    int base = blockIdx.x * blockDim.x + threadIdx.x;
    for (int i = base; i < n * HD * T; i += stride) g_mi[i] = 0.0f;
    for (int i = base; i < n * 3 * T;  i += stride) g_agg[i] = 0.0f;
    for (int i = base; i < n;          i += stride) g_cnt[i] = 0.0f;
}

__global__ __launch_bounds__(128) void edge_kernel(
    const float* __restrict__ x, const float* __restrict__ h,
    const int* __restrict__ ei, const float* __restrict__ ea,
    const float* __restrict__ w1, const float* __restrict__ b1,
    const float* __restrict__ w2, const float* __restrict__ b2,
    const float* __restrict__ cw1, const float* __restrict__ cb1,
    const float* __restrict__ cw2, const float* __restrict__ cb2,
    int E)
{
    __shared__ __align__(16) float s_in[KIN][RPB];
    __shared__ __align__(16) float s_a[HD][RPB];
    __shared__ __align__(16) float s_b[HD][RPB];
    __shared__ int   s_row[EPB], s_col[EPB];
    __shared__ float s_xij[EPB][3][T];

    const int tid = threadIdx.x;
    const int e0  = blockIdx.x * EPB;

    if (tid < EPB) {
        int e = e0 + tid;
        int ok = e < E;
        s_row[tid] = ok ? ei[e]     : 0;
        s_col[tid] = ok ? ei[E + e] : 0;
    }
    __syncthreads();

    // x_ij + squared norm (channel 128)
    if (tid < RPB) {
        int e = tid >> 2, t = tid & 3;
        int r = s_row[e], c = s_col[e];
        float n2 = 0.0f;
#pragma unroll
        for (int d = 0; d < 3; d++) {
            float v = x[(r * 3 + d) * T + t] - x[(c * 3 + d) * T + t];
            s_xij[e][d][t] = v;
            n2 += v * v;
        }
        s_in[128][tid] = n2;
    }

    // h gathers: channels 0..127 (h[row] then h[col]), 2048 items
#pragma unroll
    for (int it = 0; it < 16; it++) {
        int idx = it * 128 + tid;
        int k = idx >> 4, i = idx & 15;
        int e = i >> 2,   t = i & 3;
        float v = (k < HH) ? h[(s_row[e] * HH + k) * T + t]
                           : h[(s_col[e] * HH + (k - HH)) * T + t];
        s_in[k][i] = v;
    }
    // edge_attr: channels 129..144, 256 items
#pragma unroll
    for (int it = 0; it < 2; it++) {
        int idx = it * 128 + tid;
        int k = idx >> 4, i = idx & 15;
        int e = i >> 2,   t = i & 3;
        int ee = e0 + e;
        s_in[129 + k][i] = (ee < E) ? ea[(ee * HE + k) * T + t] : 0.0f;
    }
    __syncthreads();

    // edge MLP: silu(silu(m_in@W1+b1)@W2+b2)
    gemm_tile<KIN, HD, true>(s_in, w1, b1, s_a, tid);
    __syncthreads();
    gemm_tile<HD, HD, true>(s_a, w2, b2, s_b, tid);
    __syncthreads();

    // scatter m_ij into m_i[row]
    {
#pragma unroll
        for (int i = 0; i < RPB; i++) {
            int e = i >> 2, t = i & 3;
            if (e0 + e < E)
                atomicAdd(&g_mi[(s_row[e] * HD + tid) * T + t], s_b[tid][i]);
        }
    }

    // coord MLP layer 1 (silu)
    gemm_tile<HD, HD, true>(s_b, cw1, cb1, s_a, tid);
    __syncthreads();   // all threads done reading s_b before we overwrite it

    // weighted terms for the 128->1 projection
    {
        float wj = cw2[tid];
#pragma unroll
        for (int i = 0; i < RPB; i++) s_b[tid][i] = s_a[tid][i] * wj;
    }
    __syncthreads();

    if (tid < RPB) {
        int e = tid >> 2, t = tid & 3;
        if (e0 + e < E) {
            float c = cb2[0];
            for (int j = 0; j < HD; j++) c += s_b[j][tid];
            float n2 = s_in[128][tid];
            c = c / (sqrtf(n2 + EPSF) + 1.0f);
            int r = s_row[e];
#pragma unroll
            for (int d = 0; d < 3; d++)
                atomicAdd(&g_agg[(r * 3 + d) * T + t], c * s_xij[e][d][t]);
            if (t == 0) atomicAdd(&g_cnt[r], 1.0f);
        }
    }
}

__global__ __launch_bounds__(128) void node_kernel(
    const float* __restrict__ x, const float* __restrict__ h,
    const float* __restrict__ nw1, const float* __restrict__ nb1,
    const float* __restrict__ nw2, const float* __restrict__ nb2,
    float* __restrict__ out_x, float* __restrict__ out_h, int N)
{
    __shared__ __align__(16) float s_in[NKIN][RPB];
    __shared__ __align__(16) float s_a[HD][RPB];

    const int tid = threadIdx.x;
    const int n0  = blockIdx.x * NPB;

    // x_new epilogue (independent of smem)
    if (tid < NPB * 12) {
        int n = n0 + tid / 12;
        if (n < N) {
            int rem = tid % 12, d = rem >> 2, t = rem & 3;
            float cv = fmaxf(g_cnt[n], 1.0f);
            int off = (n * 3 + d) * T + t;
            out_x[off] = x[off] + g_agg[off] / cv;
        }
    }

    // fill h_cat = [h (64) | m_i (128)]: 3072 items
#pragma unroll
    for (int it = 0; it < 24; it++) {
        int idx = it * 128 + tid;
        int k = idx >> 4, i = idx & 15;
        int n = n0 + (i >> 2), t = i & 3;
        int nn = (n < N) ? n : 0;
        float v = (k < HH) ? h[(nn * HH + k) * T + t]
                           : g_mi[(nn * HD + (k - HH)) * T + t];
        s_in[k][i] = v;
    }
    __syncthreads();

    gemm_tile<NKIN, HD, true>(s_in, nw1, nb1, s_a, tid);
    __syncthreads();

    // second GEMM: 128 -> 64, linear
    if (tid < HH) {
        float acc[RPB];
        float bj = nb2[tid];
#pragma unroll
        for (int i = 0; i < RPB; i++) acc[i] = bj;
#pragma unroll 4
        for (int k = 0; k < HD; k++) {
            float w = nw2[k * HH + tid];
            const float4* pp = reinterpret_cast<const float4*>(s_a[k]);
            FMA16(acc, pp, w);
        }
#pragma unroll
        for (int i = 0; i < RPB; i++) {
            int n = n0 + (i >> 2), t = i & 3;
            if (n < N) out_h[(n * HH + tid) * T + t] = acc[i];
        }
    }
}

extern "C" void kernel_launch(void* const* d_in, const int* in_sizes, int n_in,
                              void* d_out, int out_size)
{
    const float* x   = (const float*)d_in[0];
    const float* h   = (const float*)d_in[1];
    const int*   ei  = (const int*)  d_in[2];
    const float* ea  = (const float*)d_in[3];
    // d_in[4] = batch (unused)
    const float* ew1 = (const float*)d_in[5];
    const float* eb1 = (const float*)d_in[6];
    const float* ew2 = (const float*)d_in[7];
    const float* eb2 = (const float*)d_in[8];
    const float* cw1 = (const float*)d_in[9];
    const float* cb1 = (const float*)d_in[10];
    const float* cw2 = (const float*)d_in[11];
    const float* cb2 = (const float*)d_in[12];
    const float* nw1 = (const float*)d_in[13];
    const float* nb1 = (const float*)d_in[14];
    const float* nw2 = (const float*)d_in[15];
    const float* nb2 = (const float*)d_in[16];

    int N = in_sizes[0] / (3 * T);
    int E = in_sizes[3] / (HE * T);

    float* out_x = (float*)d_out;
    float* out_h = out_x + (size_t)N * 3 * T;

    zero_kernel<<<2048, 256>>>(N);
    edge_kernel<<<(E + EPB - 1) / EPB, 128>>>(x, h, ei, ea,
                                              ew1, eb1, ew2, eb2,
                                              cw1, cb1, cw2, cb2, E);
    node_kernel<<<(N + NPB - 1) / NPB, 128>>>(x, h, nw1, nb1, nw2, nb2,
                                              out_x, out_h, N);
}

// round 2
// speedup vs baseline: 1.0670x; 1.0670x over previous
#include <cuda_runtime.h>

#define T   4
#define HH  64
#define HE  16
#define HD  128
#define KIN 145          // 2*HH + 1 + HE
#define NKIN 192         // HH + HD
#define EPB 4            // edges per block
#define NPB 4            // nodes per block
#define RPB 16           // rows per block (EPB*T == NPB*T)
#define MAXN 20000
#define EPSF 1e-8f

typedef unsigned long long u64;

// Scratch (device globals — no allocation allowed)
__device__ float g_mi[MAXN * HD * T];   // segment-summed m_ij  [N,HD,T]
__device__ float g_agg[MAXN * 3 * T];   // coord aggregate      [N,3,T]
__device__ float g_cnt[MAXN];           // edge counts          [N]

__device__ __forceinline__ float silu_f(float v) {
    return v / (1.0f + __expf(-v));
}

// packed fp32x2 FMA: d = a*b + d  (Blackwell FFMA2)
#define FMA2(d, a, b) asm("fma.rn.f32x2 %0, %1, %2, %0;" : "+l"(d) : "l"(a), "l"(b))

__device__ __forceinline__ u64 pack2(float v) {
    u64 r;
    asm("mov.b64 %0, {%1, %1};" : "=l"(r) : "f"(v));
    return r;
}
__device__ __forceinline__ void unpack2(u64 v, float& lo, float& hi) {
    asm("mov.b64 {%0, %1}, %2;" : "=f"(lo), "=f"(hi) : "l"(v));
}

// One 16-row x OUTD tile GEMM using packed f32x2 math.
// dst[j][i] = act(bias[j] + sum_k src[k][i]*W[k*OUTD+j]), j = calling thread's channel.
template<int K, int OUTD, bool ACT>
__device__ __forceinline__ void gemm_tile2(
    const float (* __restrict__ src)[RPB],
    const float* __restrict__ W,
    const float* __restrict__ bias,
    float (* __restrict__ dst)[RPB],
    int j)
{
    u64 acc[8];
    u64 bp = pack2(bias[j]);
#pragma unroll
    for (int i = 0; i < 8; i++) acc[i] = bp;
#pragma unroll 4
    for (int k = 0; k < K; k++) {
        u64 wp = pack2(W[k * OUTD + j]);
        const ulonglong2* pp = reinterpret_cast<const ulonglong2*>(src[k]);
        ulonglong2 p0 = pp[0], p1 = pp[1];
        FMA2(acc[0], p0.x, wp); FMA2(acc[1], p0.y, wp);
        FMA2(acc[2], p1.x, wp); FMA2(acc[3], p1.y, wp);
        ulonglong2 p2 = pp[2], p3 = pp[3];
        FMA2(acc[4], p2.x, wp); FMA2(acc[5], p2.y, wp);
        FMA2(acc[6], p3.x, wp); FMA2(acc[7], p3.y, wp);
    }
#pragma unroll
    for (int i = 0; i < 8; i++) {
        float lo, hi;
        unpack2(acc[i], lo, hi);
        dst[j][2 * i]     = ACT ? silu_f(lo) : lo;
        dst[j][2 * i + 1] = ACT ? silu_f(hi) : hi;
    }
}

__global__ void zero_kernel(int n) {
    int stride = gridDim.x * blockDim.x;
    int base = blockIdx.x * blockDim.x + threadIdx.x;
    for (int i = base; i < n * HD * T; i += stride) g_mi[i] = 0.0f;
    for (int i = base; i < n * 3 * T;  i += stride) g_agg[i] = 0.0f;
    for (int i = base; i < n;          i += stride) g_cnt[i] = 0.0f;
}

__global__ __launch_bounds__(128) void edge_kernel(
    const float* __restrict__ x, const float* __restrict__ h,
    const int* __restrict__ ei, const float* __restrict__ ea,
    const float* __restrict__ w1, const float* __restrict__ b1,
    const float* __restrict__ w2, const float* __restrict__ b2,
    const float* __restrict__ cw1, const float* __restrict__ cb1,
    const float* __restrict__ cw2, const float* __restrict__ cb2,
    int E)
{
    __shared__ __align__(16) float s_in[KIN][RPB];
    __shared__ __align__(16) float s_a[HD][RPB];
    __shared__ __align__(16) float s_b[HD][RPB];
    __shared__ int   s_row[EPB], s_col[EPB];
    __shared__ float s_xij[EPB][3][T];

    const int tid = threadIdx.x;
    const int e0  = blockIdx.x * EPB;

    if (tid < EPB) {
        int e = e0 + tid;
        int ok = e < E;
        s_row[tid] = ok ? ei[e]     : 0;
        s_col[tid] = ok ? ei[E + e] : 0;
    }
    __syncthreads();

    // x_ij + squared norm (channel 128)
    if (tid < RPB) {
        int e = tid >> 2, t = tid & 3;
        int r = s_row[e], c = s_col[e];
        float n2 = 0.0f;
#pragma unroll
        for (int d = 0; d < 3; d++) {
            float v = x[(r * 3 + d) * T + t] - x[(c * 3 + d) * T + t];
            s_xij[e][d][t] = v;
            n2 += v * v;
        }
        s_in[128][tid] = n2;
    }

    // h gathers: channels 0..127 (h[row] then h[col]), 2048 items
#pragma unroll
    for (int it = 0; it < 16; it++) {
        int idx = it * 128 + tid;
        int k = idx >> 4, i = idx & 15;
        int e = i >> 2,   t = i & 3;
        float v = (k < HH) ? h[(s_row[e] * HH + k) * T + t]
                           : h[(s_col[e] * HH + (k - HH)) * T + t];
        s_in[k][i] = v;
    }
    // edge_attr: channels 129..144, 256 items
#pragma unroll
    for (int it = 0; it < 2; it++) {
        int idx = it * 128 + tid;
        int k = idx >> 4, i = idx & 15;
        int e = i >> 2,   t = i & 3;
        int ee = e0 + e;
        s_in[129 + k][i] = (ee < E) ? ea[(ee * HE + k) * T + t] : 0.0f;
    }
    __syncthreads();

    // edge MLP: silu(silu(m_in@W1+b1)@W2+b2)
    gemm_tile2<KIN, HD, true>(s_in, w1, b1, s_a, tid);
    __syncthreads();
    gemm_tile2<HD, HD, true>(s_a, w2, b2, s_b, tid);
    __syncthreads();

    // scatter m_ij into m_i[row] — vector red, 4 floats (t=0..3) per op
    {
#pragma unroll
        for (int e = 0; e < EPB; e++) {
            if (e0 + e < E) {
                const float4 v = *reinterpret_cast<const float4*>(&s_b[tid][e * 4]);
                float* p = &g_mi[(s_row[e] * HD + tid) * T];
                asm volatile("red.global.add.v4.f32 [%0], {%1,%2,%3,%4};"
                             :: "l"(p), "f"(v.x), "f"(v.y), "f"(v.z), "f"(v.w)
                             : "memory");
            }
        }
    }

    // coord MLP layer 1 (silu)
    gemm_tile2<HD, HD, true>(s_b, cw1, cb1, s_a, tid);
    __syncthreads();   // all threads done reading s_b before we overwrite it

    // weighted terms for the 128->1 projection
    {
        float wj = cw2[tid];
#pragma unroll
        for (int i = 0; i < RPB; i++) s_b[tid][i] = s_a[tid][i] * wj;
    }
    __syncthreads();

    if (tid < RPB) {
        int e = tid >> 2, t = tid & 3;
        if (e0 + e < E) {
            float c = cb2[0];
            for (int j = 0; j < HD; j++) c += s_b[j][tid];
            float n2 = s_in[128][tid];
            c = c / (sqrtf(n2 + EPSF) + 1.0f);
            int r = s_row[e];
#pragma unroll
            for (int d = 0; d < 3; d++)
                atomicAdd(&g_agg[(r * 3 + d) * T + t], c * s_xij[e][d][t]);
            if (t == 0) atomicAdd(&g_cnt[r], 1.0f);
        }
    }
}

__global__ __launch_bounds__(128) void node_kernel(
    const float* __restrict__ x, const float* __restrict__ h,
    const float* __restrict__ nw1, const float* __restrict__ nb1,
    const float* __restrict__ nw2, const float* __restrict__ nb2,
    float* __restrict__ out_x, float* __restrict__ out_h, int N)
{
    __shared__ __align__(16) float s_in[NKIN][RPB];
    __shared__ __align__(16) float s_a[HD][RPB];

    const int tid = threadIdx.x;
    const int n0  = blockIdx.x * NPB;

    // x_new epilogue (independent of smem)
    if (tid < NPB * 12) {
        int n = n0 + tid / 12;
        if (n < N) {
            int rem = tid % 12, d = rem >> 2, t = rem & 3;
            float cv = fmaxf(g_cnt[n], 1.0f);
            int off = (n * 3 + d) * T + t;
            out_x[off] = x[off] + g_agg[off] / cv;
        }
    }

    // fill h_cat = [h (64) | m_i (128)]: 3072 items
#pragma unroll
    for (int it = 0; it < 24; it++) {
        int idx = it * 128 + tid;
        int k = idx >> 4, i = idx & 15;
        int n = n0 + (i >> 2), t = i & 3;
        int nn = (n < N) ? n : 0;
        float v = (k < HH) ? h[(nn * HH + k) * T + t]
                           : g_mi[(nn * HD + (k - HH)) * T + t];
        s_in[k][i] = v;
    }
    __syncthreads();

    gemm_tile2<NKIN, HD, true>(s_in, nw1, nb1, s_a, tid);
    __syncthreads();

    // second GEMM: 128 -> 64, linear, packed f32x2
    if (tid < HH) {
        u64 acc[8];
        u64 bp = pack2(nb2[tid]);
#pragma unroll
        for (int i = 0; i < 8; i++) acc[i] = bp;
#pragma unroll 4
        for (int k = 0; k < HD; k++) {
            u64 wp = pack2(nw2[k * HH + tid]);
            const ulonglong2* pp = reinterpret_cast<const ulonglong2*>(s_a[k]);
            ulonglong2 p0 = pp[0], p1 = pp[1];
            FMA2(acc[0], p0.x, wp); FMA2(acc[1], p0.y, wp);
            FMA2(acc[2], p1.x, wp); FMA2(acc[3], p1.y, wp);
            ulonglong2 p2 = pp[2], p3 = pp[3];
            FMA2(acc[4], p2.x, wp); FMA2(acc[5], p2.y, wp);
            FMA2(acc[6], p3.x, wp); FMA2(acc[7], p3.y, wp);
        }
#pragma unroll
        for (int nl = 0; nl < NPB; nl++) {
            int n = n0 + nl;
            if (n < N) {
                float4 o;
                unpack2(acc[2 * nl],     o.x, o.y);
                unpack2(acc[2 * nl + 1], o.z, o.w);
                *reinterpret_cast<float4*>(&out_h[(n * HH + tid) * T]) = o;
            }
        }
    }
}

extern "C" void kernel_launch(void* const* d_in, const int* in_sizes, int n_in,
                              void* d_out, int out_size)
{
    const float* x   = (const float*)d_in[0];
    const float* h   = (const float*)d_in[1];
    const int*   ei  = (const int*)  d_in[2];
    const float* ea  = (const float*)d_in[3];
    // d_in[4] = batch (unused)
    const float* ew1 = (const float*)d_in[5];
    const float* eb1 = (const float*)d_in[6];
    const float* ew2 = (const float*)d_in[7];
    const float* eb2 = (const float*)d_in[8];
    const float* cw1 = (const float*)d_in[9];
    const float* cb1 = (const float*)d_in[10];
    const float* cw2 = (const float*)d_in[11];
    const float* cb2 = (const float*)d_in[12];
    const float* nw1 = (const float*)d_in[13];
    const float* nb1 = (const float*)d_in[14];
    const float* nw2 = (const float*)d_in[15];
    const float* nb2 = (const float*)d_in[16];

    int N = in_sizes[0] / (3 * T);
    int E = in_sizes[3] / (HE * T);

    float* out_x = (float*)d_out;
    float* out_h = out_x + (size_t)N * 3 * T;

    zero_kernel<<<2048, 256>>>(N);
    edge_kernel<<<(E + EPB - 1) / EPB, 128>>>(x, h, ei, ea,
                                              ew1, eb1, ew2, eb2,
                                              cw1, cb1, cw2, cb2, E);
    node_kernel<<<(N + NPB - 1) / NPB, 128>>>(x, h, nw1, nb1, nw2, nb2,
                                              out_x, out_h, N);
}

// round 3
// speedup vs baseline: 1.5367x; 1.4402x over previous
#include <cuda_runtime.h>

#define T    4
#define HH   64
#define HE   16
#define HD   128
#define KIN  145         // 2*HH + 1 + HE
#define KPAD 160         // KIN rounded to 32
#define NKIN 192
#define EPB  32          // edges per edge-block
#define ROWS 128         // EPB*T rows per block
#define STRIDE 132       // padded row length (floats) in A buffer
#define NPB  4
#define RPB  16
#define MAXN 20000
#define EPSF 1e-8f

typedef unsigned long long u64;

// Scratch (device globals — no allocation allowed)
__device__ float g_mi[MAXN * HD * T];   // segment-summed m_ij  [N,HD,T]
__device__ float g_agg[MAXN * 3 * T];   // coord aggregate      [N,3,T]
__device__ float g_cnt[MAXN];           // edge counts          [N]

__device__ __forceinline__ float silu_f(float v) {
    return v / (1.0f + __expf(-v));
}

// packed fp32x2 FMA: d = a*b + d  (Blackwell FFMA2)
#define FMA2(d, a, b) asm("fma.rn.f32x2 %0, %1, %2, %0;" : "+l"(d) : "l"(a), "l"(b))

__device__ __forceinline__ u64 pack2(float v) {
    u64 r; asm("mov.b64 %0, {%1, %1};" : "=l"(r) : "f"(v)); return r;
}
__device__ __forceinline__ u64 packab(float a, float b) {
    u64 r; asm("mov.b64 %0, {%1, %2};" : "=l"(r) : "f"(a), "f"(b)); return r;
}
__device__ __forceinline__ void unpack2(u64 v, float& lo, float& hi) {
    asm("mov.b64 {%0, %1}, %2;" : "=f"(lo), "=f"(hi) : "l"(v));
}

// ---------------------------------------------------------------------------
// Register-tiled GEMM phase over a 128-row x 128-col tile.
// A in smem (sA, channel-major, STRIDE floats per channel row).
// W streamed from global through sW in 32-k chunks (register prefetch).
// Thread (ty,tx): rows ty*8..+7; cols {4tx..4tx+3} u {64+4tx..+3}.
// out[r][c]: c 0..3 -> col 4tx+c ; c 4..7 -> col 60+4tx+c.
// ---------------------------------------------------------------------------
template<int NCHUNK, int KLIM, bool ACT>
__device__ __forceinline__ void gemm_phase(
    const float* __restrict__ sA, float* __restrict__ sW,
    const float* __restrict__ gW, const float* __restrict__ gB,
    int tid, int tx, int ty, float (&out)[8][8])
{
    u64 acc[8][4];
    {
        float4 bA = *(const float4*)(gB + 4 * tx);
        float4 bB = *(const float4*)(gB + 64 + 4 * tx);
        u64 i0 = packab(bA.x, bA.y), i1 = packab(bA.z, bA.w);
        u64 i2 = packab(bB.x, bB.y), i3 = packab(bB.z, bB.w);
#pragma unroll
        for (int r = 0; r < 8; r++) {
            acc[r][0] = i0; acc[r][1] = i1; acc[r][2] = i2; acc[r][3] = i3;
        }
    }

    float4 pre[4];
#pragma unroll
    for (int i = 0; i < 4; i++) {
        int off = i * 1024 + tid * 4;
        int kg = off >> 7;
        pre[i] = (kg < KLIM) ? *(const float4*)(gW + kg * HD + (off & 127))
                             : make_float4(0.f, 0.f, 0.f, 0.f);
    }

#pragma unroll 1
    for (int kc = 0; kc < NCHUNK; kc++) {
        __syncthreads();                       // prev chunk consumers done
#pragma unroll
        for (int i = 0; i < 4; i++)
            *(float4*)(sW + i * 1024 + tid * 4) = pre[i];
        __syncthreads();
        if (kc + 1 < NCHUNK) {
#pragma unroll
            for (int i = 0; i < 4; i++) {
                int off = i * 1024 + tid * 4;
                int kg = (kc + 1) * 32 + (off >> 7);
                pre[i] = (kg < KLIM) ? *(const float4*)(gW + kg * HD + (off & 127))
                                     : make_float4(0.f, 0.f, 0.f, 0.f);
            }
        }
        const float* ap = sA + (kc * 32) * STRIDE + ty * 8;
#pragma unroll 8
        for (int kk = 0; kk < 32; kk++) {
            float4 a0 = *(const float4*)(ap);
            float4 a1 = *(const float4*)(ap + 4);
            ap += STRIDE;
            ulonglong2 bA = *(const ulonglong2*)(sW + kk * HD + 4 * tx);
            ulonglong2 bB = *(const ulonglong2*)(sW + kk * HD + 64 + 4 * tx);
            float av[8] = {a0.x, a0.y, a0.z, a0.w, a1.x, a1.y, a1.z, a1.w};
#pragma unroll
            for (int r = 0; r < 8; r++) {
                u64 ar = pack2(av[r]);
                FMA2(acc[r][0], ar, bA.x);
                FMA2(acc[r][1], ar, bA.y);
                FMA2(acc[r][2], ar, bB.x);
                FMA2(acc[r][3], ar, bB.y);
            }
        }
    }

#pragma unroll
    for (int r = 0; r < 8; r++)
#pragma unroll
        for (int cp = 0; cp < 4; cp++) {
            float lo, hi; unpack2(acc[r][cp], lo, hi);
            out[r][cp * 2]     = ACT ? silu_f(lo) : lo;
            out[r][cp * 2 + 1] = ACT ? silu_f(hi) : hi;
        }
}

__global__ void zero_kernel(int n) {
    int stride = gridDim.x * blockDim.x;
    int base = blockIdx.x * blockDim.x + threadIdx.x;
    for (int i = base; i < n * HD * T; i += stride) g_mi[i] = 0.0f;
    for (int i = base; i < n * 3 * T;  i += stride) g_agg[i] = 0.0f;
    for (int i = base; i < n;          i += stride) g_cnt[i] = 0.0f;
}

__global__ __launch_bounds__(256, 2) void edge_kernel(
    const float* __restrict__ x, const float* __restrict__ h,
    const int* __restrict__ ei, const float* __restrict__ ea,
    const float* __restrict__ w1, const float* __restrict__ b1,
    const float* __restrict__ w2, const float* __restrict__ b2,
    const float* __restrict__ cw1, const float* __restrict__ cb1,
    const float* __restrict__ cw2, const float* __restrict__ cb2,
    int E)
{
    extern __shared__ float sm[];
    float* s_buf = sm;                         // KPAD*STRIDE floats (A/mid/m_ij)
    float* s_w   = sm + KPAD * STRIDE;         // 32*HD floats
    float* s_part = s_buf;                     // 16*ROWS, overlays s_buf late

    __shared__ int   s_rown[EPB], s_coln[EPB];
    __shared__ float s_xij[EPB][3][T];
    __shared__ float s_n2[ROWS];

    const int tid = threadIdx.x;
    const int tx  = tid & 15;
    const int ty  = tid >> 4;
    const int e0  = blockIdx.x * EPB;

    if (tid < EPB) {
        int eg = e0 + tid;
        if (eg >= E) eg = E - 1;
        s_rown[tid] = ei[eg];
        s_coln[tid] = ei[E + eg];
    }
    __syncthreads();

    // ---- gather: h[row] (ch 0..63), h[col] (64..127) — float4 over t ----
#pragma unroll
    for (int it = 0; it < 16; it++) {
        int idx  = it * 256 + tid;             // 4096 float4 items
        int k    = idx & 63;
        int e    = (idx >> 6) & 31;
        int side = idx >> 11;
        int node = side ? s_coln[e] : s_rown[e];
        float4 v = *(const float4*)(h + ((size_t)node * HH + k) * T);
        *(float4*)(s_buf + (side * HH + k) * STRIDE + e * 4) = v;
    }
    // ---- edge_attr: ch 129..144 ----
#pragma unroll
    for (int it = 0; it < 2; it++) {
        int idx = it * 256 + tid;              // 512 items
        int k = idx & 15;
        int e = idx >> 4;
        int eg = e0 + e; if (eg >= E) eg = E - 1;
        float4 v = *(const float4*)(ea + ((size_t)eg * HE + k) * T);
        *(float4*)(s_buf + (129 + k) * STRIDE + e * 4) = v;
    }
    // ---- zero pad channels 145..159 ----
    for (int i = tid; i < 15 * 32; i += 256) {
        int k = 145 + (i >> 5);
        *(float4*)(s_buf + k * STRIDE + (i & 31) * 4) = make_float4(0.f, 0.f, 0.f, 0.f);
    }
    // ---- x_ij, n2 (ch 128) ----
    if (tid < ROWS) {
        int e = tid >> 2, t = tid & 3;
        int rn = s_rown[e], cn = s_coln[e];
        float n2 = 0.f;
#pragma unroll
        for (int d = 0; d < 3; d++) {
            float v = x[((size_t)rn * 3 + d) * T + t] - x[((size_t)cn * 3 + d) * T + t];
            s_xij[e][d][t] = v;
            n2 += v * v;
        }
        s_buf[128 * STRIDE + tid] = n2;
        s_n2[tid] = n2;
    }
    // (gemm_phase's first __syncthreads covers gather->compute ordering)

    // ---- layer 1: silu(A @ W1 + b1) ----
    float o1[8][8];
    gemm_phase<5, KIN, true>(s_buf, s_w, w1, b1, tid, tx, ty, o1);

    __syncthreads();                           // all A reads done
#pragma unroll
    for (int c = 0; c < 8; c++) {
        int col = (c < 4) ? 4 * tx + c : 60 + 4 * tx + c;
        *(float4*)(s_buf + col * STRIDE + ty * 8) =
            make_float4(o1[0][c], o1[1][c], o1[2][c], o1[3][c]);
        *(float4*)(s_buf + col * STRIDE + ty * 8 + 4) =
            make_float4(o1[4][c], o1[5][c], o1[6][c], o1[7][c]);
    }
    __syncthreads();

    // ---- layer 2: m_ij = silu(mid @ W2 + b2) ----
    float o2[8][8];
    gemm_phase<4, HD, true>(s_buf, s_w, w2, b2, tid, tx, ty, o2);

    // ---- scatter m_i ----
#pragma unroll
    for (int eh = 0; eh < 2; eh++) {
        int el = 2 * ty + eh;
        if (e0 + el < E) {
            int node = s_rown[el];
#pragma unroll
            for (int c = 0; c < 8; c++) {
                int col = (c < 4) ? 4 * tx + c : 60 + 4 * tx + c;
                float* p = &g_mi[((size_t)node * HD + col) * T];
                asm volatile("red.global.add.v4.f32 [%0], {%1,%2,%3,%4};"
                             :: "l"(p), "f"(o2[eh * 4 + 0][c]), "f"(o2[eh * 4 + 1][c]),
                                "f"(o2[eh * 4 + 2][c]), "f"(o2[eh * 4 + 3][c])
                             : "memory");
            }
        }
    }

    // ---- m_ij -> smem for coord MLP ----
    __syncthreads();
#pragma unroll
    for (int c = 0; c < 8; c++) {
        int col = (c < 4) ? 4 * tx + c : 60 + 4 * tx + c;
        *(float4*)(s_buf + col * STRIDE + ty * 8) =
            make_float4(o2[0][c], o2[1][c], o2[2][c], o2[3][c]);
        *(float4*)(s_buf + col * STRIDE + ty * 8 + 4) =
            make_float4(o2[4][c], o2[5][c], o2[6][c], o2[7][c]);
    }
    __syncthreads();

    // ---- coord layer 1: silu(m_ij @ cw1 + cb1) ----
    float o3[8][8];
    gemm_phase<4, HD, true>(s_buf, s_w, cw1, cb1, tid, tx, ty, o3);

    // ---- coord projection to 1: partials ----
    {
        float4 c2a = *(const float4*)(cw2 + 4 * tx);
        float4 c2b = *(const float4*)(cw2 + 64 + 4 * tx);
        float cw[8] = {c2a.x, c2a.y, c2a.z, c2a.w, c2b.x, c2b.y, c2b.z, c2b.w};
        float p[8];
#pragma unroll
        for (int r = 0; r < 8; r++) {
            float s = 0.f;
#pragma unroll
            for (int c = 0; c < 8; c++) s += o3[r][c] * cw[c];
            p[r] = s;
        }
        __syncthreads();                       // s_buf reads (GEMM3) done
        *(float4*)(s_part + tx * ROWS + ty * 8) = make_float4(p[0], p[1], p[2], p[3]);
        *(float4*)(s_part + tx * ROWS + ty * 8 + 4) = make_float4(p[4], p[5], p[6], p[7]);
    }
    __syncthreads();

    if (tid < ROWS) {
        float cval = cb2[0];
#pragma unroll
        for (int q = 0; q < 16; q++) cval += s_part[q * ROWS + tid];
        cval /= (sqrtf(s_n2[tid] + EPSF) + 1.0f);
        int e = tid >> 2, t = tid & 3;
        if (e0 + e < E) {
            int node = s_rown[e];
#pragma unroll
            for (int d = 0; d < 3; d++)
                atomicAdd(&g_agg[((size_t)node * 3 + d) * T + t], cval * s_xij[e][d][t]);
            if (t == 0) atomicAdd(&g_cnt[node], 1.0f);
        }
    }
}

// ---------------------------------------------------------------------------
// Node kernel (unchanged structure from round 2)
// ---------------------------------------------------------------------------
__global__ __launch_bounds__(128) void node_kernel(
    const float* __restrict__ x, const float* __restrict__ h,
    const float* __restrict__ nw1, const float* __restrict__ nb1,
    const float* __restrict__ nw2, const float* __restrict__ nb2,
    float* __restrict__ out_x, float* __restrict__ out_h, int N)
{
    __shared__ __align__(16) float s_in[NKIN][RPB];
    __shared__ __align__(16) float s_a[HD][RPB];

    const int tid = threadIdx.x;
    const int n0  = blockIdx.x * NPB;

    if (tid < NPB * 12) {
        int n = n0 + tid / 12;
        if (n < N) {
            int rem = tid % 12, d = rem >> 2, t = rem & 3;
            float cv = fmaxf(g_cnt[n], 1.0f);
            int off = (n * 3 + d) * T + t;
            out_x[off] = x[off] + g_agg[off] / cv;
        }
    }

#pragma unroll
    for (int it = 0; it < 24; it++) {
        int idx = it * 128 + tid;
        int k = idx >> 4, i = idx & 15;
        int n = n0 + (i >> 2), t = i & 3;
        int nn = (n < N) ? n : 0;
        float v = (k < HH) ? h[(nn * HH + k) * T + t]
                           : g_mi[(nn * HD + (k - HH)) * T + t];
        s_in[k][i] = v;
    }
    __syncthreads();

    // layer 1: 192 -> 128, silu
    {
        u64 acc[8];
        u64 bp = pack2(nb1[tid]);
#pragma unroll
        for (int i = 0; i < 8; i++) acc[i] = bp;
#pragma unroll 4
        for (int k = 0; k < NKIN; k++) {
            u64 wp = pack2(nw1[k * HD + tid]);
            const ulonglong2* pp = reinterpret_cast<const ulonglong2*>(s_in[k]);
            ulonglong2 p0 = pp[0], p1 = pp[1];
            FMA2(acc[0], p0.x, wp); FMA2(acc[1], p0.y, wp);
            FMA2(acc[2], p1.x, wp); FMA2(acc[3], p1.y, wp);
            ulonglong2 p2 = pp[2], p3 = pp[3];
            FMA2(acc[4], p2.x, wp); FMA2(acc[5], p2.y, wp);
            FMA2(acc[6], p3.x, wp); FMA2(acc[7], p3.y, wp);
        }
#pragma unroll
        for (int i = 0; i < 8; i++) {
            float lo, hi; unpack2(acc[i], lo, hi);
            s_a[tid][2 * i]     = silu_f(lo);
            s_a[tid][2 * i + 1] = silu_f(hi);
        }
    }
    __syncthreads();

    // layer 2: 128 -> 64, linear
    if (tid < HH) {
        u64 acc[8];
        u64 bp = pack2(nb2[tid]);
#pragma unroll
        for (int i = 0; i < 8; i++) acc[i] = bp;
#pragma unroll 4
        for (int k = 0; k < HD; k++) {
            u64 wp = pack2(nw2[k * HH + tid]);
            const ulonglong2* pp = reinterpret_cast<const ulonglong2*>(s_a[k]);
            ulonglong2 p0 = pp[0], p1 = pp[1];
            FMA2(acc[0], p0.x, wp); FMA2(acc[1], p0.y, wp);
            FMA2(acc[2], p1.x, wp); FMA2(acc[3], p1.y, wp);
            ulonglong2 p2 = pp[2], p3 = pp[3];
            FMA2(acc[4], p2.x, wp); FMA2(acc[5], p2.y, wp);
            FMA2(acc[6], p3.x, wp); FMA2(acc[7], p3.y, wp);
        }
#pragma unroll
        for (int nl = 0; nl < NPB; nl++) {
            int n = n0 + nl;
            if (n < N) {
                float4 o;
                unpack2(acc[2 * nl],     o.x, o.y);
                unpack2(acc[2 * nl + 1], o.z, o.w);
                *reinterpret_cast<float4*>(&out_h[(n * HH + tid) * T]) = o;
            }
        }
    }
}

extern "C" void kernel_launch(void* const* d_in, const int* in_sizes, int n_in,
                              void* d_out, int out_size)
{
    const float* x   = (const float*)d_in[0];
    const float* h   = (const float*)d_in[1];
    const int*   ei  = (const int*)  d_in[2];
    const float* ea  = (const float*)d_in[3];
    const float* ew1 = (const float*)d_in[5];
    const float* eb1 = (const float*)d_in[6];
    const float* ew2 = (const float*)d_in[7];
    const float* eb2 = (const float*)d_in[8];
    const float* cw1 = (const float*)d_in[9];
    const float* cb1 = (const float*)d_in[10];
    const float* cw2 = (const float*)d_in[11];
    const float* cb2 = (const float*)d_in[12];
    const float* nw1 = (const float*)d_in[13];
    const float* nb1 = (const float*)d_in[14];
    const float* nw2 = (const float*)d_in[15];
    const float* nb2 = (const float*)d_in[16];

    int N = in_sizes[0] / (3 * T);
    int E = in_sizes[3] / (HE * T);

    float* out_x = (float*)d_out;
    float* out_h = out_x + (size_t)N * 3 * T;

    const int smem_bytes = (KPAD * STRIDE + 32 * HD) * sizeof(float);
    cudaFuncSetAttribute(edge_kernel, cudaFuncAttributeMaxDynamicSharedMemorySize,
                         smem_bytes);

    zero_kernel<<<2048, 256>>>(N);
    edge_kernel<<<(E + EPB - 1) / EPB, 256, smem_bytes>>>(
        x, h, ei, ea, ew1, eb1, ew2, eb2, cw1, cb1, cw2, cb2, E);
    node_kernel<<<(N + NPB - 1) / NPB, 128>>>(x, h, nw1, nb1, nw2, nb2,
                                              out_x, out_h, N);
}